// round 15
// baseline (speedup 1.0000x reference)
#include <cuda_runtime.h>
#include <cuda_fp16.h>
#include <cstdint>

// ---------------------------------------------------------------------------
// XORConv2d: out = conv_valid(x, 1-2W), x (32,128,64,64) f32, W (256,128,3,3)
// Implicit GEMM on mma.sync fp16/fp32. sm_103 plain target (no tcgen05).
// R15: R14 (2 CTAs/SM, 128co x 124px, warp 64x32) + A-tile K-half ring of
// THREE 16KB buffers: every cp.async wait is covered by >=4 j-steps of
// compute -> zero exposed A-load latency, regardless of CTA phase alignment.
// ---------------------------------------------------------------------------

#define BDIM   32
#define CIN    128
#define HH     64
#define WWID   64
#define COUT   256
#define HOUT   62
#define WOUT   62
#define PIX_PER_IMG (HOUT*WOUT)         // 3844

__device__ __half g_x[(size_t)BDIM * HH * WWID * CIN];   // NHWC fp16, 32 MB
__device__ __half g_w[9 * COUT * CIN];                   // (1-2W), [kp][co][cin]

static __device__ __forceinline__ uint32_t smem_u32(const void* p) {
    uint32_t a;
    asm("{ .reg .u64 t; cvta.to.shared.u64 t, %1; cvt.u32.u64 %0, t; }"
        : "=r"(a) : "l"(p));
    return a;
}

// ---------------------------------------------------------------------------
// Merged prep: blocks [0,8192) transpose x NCHW f32 -> NHWC f16 (full-sector
// packed half2 writes); blocks [8192, 8192+1152) build g_w = 1-2W.
// ---------------------------------------------------------------------------
#define XBLOCKS 8192
#define WBLOCKS ((COUT*CIN*9 + 255) / 256)    // 1152

__global__ void prep_all(const float* __restrict__ x,
                         const float* __restrict__ W) {
    if (blockIdx.x < XBLOCKS) {
        __shared__ float t[64][33];
        int bid = blockIdx.x;
        int bh  = bid & 2047;              // b*64 + h
        int rest = bid >> 11;              // 0..3
        int b  = bh >> 6, h = bh & 63;
        int c0 = (rest & 1) * 64;
        int w0 = (rest >> 1) * 32;
        int l  = threadIdx.x & 31, wy = threadIdx.x >> 5;   // 8 warps

        const float* src = x + ((size_t)(b * CIN + c0)) * (HH * WWID)
                             + h * WWID + w0;
#pragma unroll
        for (int i = 0; i < 8; i++)
            t[wy + 8 * i][l] = src[(size_t)(wy + 8 * i) * (HH * WWID) + l];
        __syncthreads();

#pragma unroll
        for (int i = 0; i < 4; i++) {
            int ww = wy + 8 * i;
            __half2 v = __floats2half2_rn(t[2 * l][ww], t[2 * l + 1][ww]);
            __half* drow = g_x + ((size_t)(bh * WWID) + w0 + ww) * CIN + c0;
            ((uint32_t*)drow)[l] = *(uint32_t*)&v;
        }
    } else {
        int idx = (blockIdx.x - XBLOCKS) * 256 + threadIdx.x;
        if (idx < COUT * CIN * 9) {
            int co  = idx / (CIN * 9);
            int r   = idx - co * (CIN * 9);
            int cin = r / 9;
            int kp  = r - cin * 9;
            g_w[(kp * COUT + co) * CIN + cin] =
                __float2half_rn(1.0f - 2.0f * W[idx]);
        }
    }
}

// ---------------------------------------------------------------------------
// Main. smem per CTA: [0, 48K) A half-buffer ring (3 x 16KB; half t=2kp+h
// lives in buffer t%3, 128 rows x 128B swizzled) | [48K, 112K) patch.
// Per kp: wait h0 / sync / issue h0(kp+1) / compute j0-3 /
//         wait h1 / sync / issue h1(kp+1) / compute j4-7.
// 8 warps: 2(M) x 4(N), warp tile 64x32. grid (31, 32, 2), 256 threads.
// ---------------------------------------------------------------------------
#define AHALF  16384
#define PBOFF  (3*AHALF)                     // 49152
#define SMEM_BYTES (PBOFF + 65536)           // 114688 per CTA -> 2 CTAs/SM

__global__ void __launch_bounds__(256, 2)
xorconv_main(float* __restrict__ out) {
    extern __shared__ char smem[];
    const uint32_t sb = smem_u32(smem);
    const uint32_t PB = sb + PBOFF;

    const int tid = threadIdx.x;
    const int l   = tid & 31;
    const int w   = tid >> 5;          // 0..7
    const int wm  = w & 1;             // M group (64 co)
    const int wn  = w >> 1;            // N group (32 px)
    const int b   = blockIdx.y;
    const int r0  = blockIdx.x * 2;    // first output row
    const int co_base = blockIdx.z * 128;

    // ---- Patch: 256 contiguous g_x rows starting at (b, r0, 0) ----
    {
        const int c    = tid & 15;     // 16B chunk in a 256B row
        const int rgrp = tid >> 4;     // 16 groups
        const __half* xsrc = g_x + ((size_t)(b * (HH * WWID) + r0 * WWID)) * CIN;
#pragma unroll
        for (int i = 0; i < 16; i++) {
            int r = rgrp + 16 * i;
            uint32_t sw = (uint32_t)r * 256u + (uint32_t)((c ^ (r & 7)) * 16);
            asm volatile("cp.async.cg.shared.global [%0], [%1], 16;"
                         :: "r"(PB + sw), "l"(xsrc + (size_t)r * CIN + c * 8));
        }
    }

    // ---- A half loader: 128 rows (co) x 128B (K-half h) of tile kp ----
    const int cl = tid & 7;            // chunk within half (16B units)
    const int rg = tid >> 3;           // 0..31
    auto load_A_half = [&](int kp, int h) {
        uint32_t dst = sb + (uint32_t)(((2 * kp + h) % 3) * AHALF);
        const __half* wp = g_w + (kp * COUT + co_base) * CIN + h * 64;
#pragma unroll
        for (int i = 0; i < 4; i++) {
            int r = rg + 32 * i;
            uint32_t sw = (uint32_t)r * 128u + (uint32_t)((cl ^ (r & 7)) * 16);
            asm volatile("cp.async.cg.shared.global [%0], [%1], 16;"
                         :: "r"(dst + sw), "l"(wp + r * CIN + cl * 8));
        }
    };

    load_A_half(0, 0);
    asm volatile("cp.async.commit_group;" ::: "memory");   // G0: patch + A0h0
    load_A_half(0, 1);
    asm volatile("cp.async.commit_group;" ::: "memory");   // G1: A0h1

    // ---- Per-lane constants ----
    const uint32_t selA = (uint32_t)(l >> 4);
    const uint32_t selB = (uint32_t)((l >> 3) & 1);
    const int rowA0 = wm * 64 + (l & 15);
    int pr0[2];
#pragma unroll
    for (int nb = 0; nb < 2; nb++) {
        int n = wn * 32 + (l & 7) + ((l >> 4) << 3) + nb * 16;
        if (n > 123) n = 123;
        pr0[nb] = (n / WOUT) * WWID + (n % WOUT);
    }

    float acc[4][4][4];
#pragma unroll
    for (int a = 0; a < 4; a++)
#pragma unroll
        for (int bb = 0; bb < 4; bb++)
#pragma unroll
            for (int e = 0; e < 4; e++) acc[a][bb][e] = 0.f;

    uint32_t prow[2], pbase[2];

    // ---- Compute 4 j-steps from one A half-buffer ----
    auto run_half = [&](uint32_t Ab, int jbase) {
#pragma unroll
        for (int jl = 0; jl < 4; jl++) {
            const int j = jbase + jl;
            uint32_t a[4][4], bq[2][4];
#pragma unroll
            for (int fm = 0; fm < 4; fm++) {
                int r = rowA0 + fm * 16;
                uint32_t ch = ((uint32_t)(2 * jl) + selA) ^ (uint32_t)(r & 7);
                uint32_t ad = Ab + (uint32_t)r * 128u + ch * 16u;
                asm volatile(
                    "ldmatrix.sync.aligned.m8n8.x4.shared.b16 {%0,%1,%2,%3}, [%4];"
                    : "=r"(a[fm][0]), "=r"(a[fm][1]), "=r"(a[fm][2]), "=r"(a[fm][3])
                    : "r"(ad));
            }
#pragma unroll
            for (int nb = 0; nb < 2; nb++) {
                uint32_t ch = ((uint32_t)(2 * j) + selB) ^ (prow[nb] & 7u);
                uint32_t ad = pbase[nb] + ch * 16u;
                asm volatile(
                    "ldmatrix.sync.aligned.m8n8.x4.shared.b16 {%0,%1,%2,%3}, [%4];"
                    : "=r"(bq[nb][0]), "=r"(bq[nb][1]), "=r"(bq[nb][2]), "=r"(bq[nb][3])
                    : "r"(ad));
            }
#pragma unroll
            for (int fm = 0; fm < 4; fm++)
#pragma unroll
                for (int nf = 0; nf < 4; nf++) {
                    asm volatile(
                        "mma.sync.aligned.m16n8k16.row.col.f32.f16.f16.f32 "
                        "{%0,%1,%2,%3}, {%4,%5,%6,%7}, {%8,%9}, {%0,%1,%2,%3};"
                        : "+f"(acc[fm][nf][0]), "+f"(acc[fm][nf][1]),
                          "+f"(acc[fm][nf][2]), "+f"(acc[fm][nf][3])
                        : "r"(a[fm][0]), "r"(a[fm][1]), "r"(a[fm][2]), "r"(a[fm][3]),
                          "r"(bq[nf >> 1][(nf & 1) * 2]),
                          "r"(bq[nf >> 1][(nf & 1) * 2 + 1]));
                }
        }
    };

    for (int kp = 0; kp < 9; kp++) {
        const int kh = kp / 3, kw = kp - 3 * kh;
        const int shift = kh * WWID + kw;
#pragma unroll
        for (int nb = 0; nb < 2; nb++) {
            prow[nb]  = (uint32_t)(pr0[nb] + shift);
            pbase[nb] = PB + prow[nb] * 256u;
        }
        const uint32_t Ab0 = sb + (uint32_t)(((2 * kp)     % 3) * AHALF);
        const uint32_t Ab1 = sb + (uint32_t)(((2 * kp + 1) % 3) * AHALF);

        // -- first half --
        asm volatile("cp.async.wait_group 1;" ::: "memory");
        __syncthreads();                       // h0(kp) (+patch) visible
        if (kp < 8) load_A_half(kp + 1, 0);    // into free ring slot
        asm volatile("cp.async.commit_group;" ::: "memory");
        run_half(Ab0, 0);

        // -- second half --
        asm volatile("cp.async.wait_group 1;" ::: "memory");
        __syncthreads();                       // h1(kp) visible; h0 consumed
        if (kp < 8) load_A_half(kp + 1, 1);    // overwrites consumed h0 slot
        asm volatile("cp.async.commit_group;" ::: "memory");
        run_half(Ab1, 4);
    }

    // ---- Epilogue: direct NCHW fp32 stores (skip pad pixels n>=124) ----
#pragma unroll
    for (int fm = 0; fm < 4; fm++) {
        int m = co_base + wm * 64 + fm * 16 + (l >> 2);
        size_t mb = (size_t)(b * COUT + m) * PIX_PER_IMG;
#pragma unroll
        for (int nf = 0; nf < 4; nf++) {
            int n0 = wn * 32 + nf * 8 + (l & 3) * 2;
#pragma unroll
            for (int e = 0; e < 2; e++) {
                int n = n0 + e;
                if (n < 124) {
                    int ho = r0 + (n >= WOUT ? 1 : 0);
                    int wo = n - (n >= WOUT ? WOUT : 0);
                    size_t idx = mb + (size_t)ho * WOUT + wo;
                    out[idx]                              = acc[fm][nf][e];
                    out[idx + (size_t)8 * PIX_PER_IMG]    = acc[fm][nf][2 + e];
                }
            }
        }
    }
}

// ---------------------------------------------------------------------------
extern "C" void kernel_launch(void* const* d_in, const int* in_sizes, int n_in,
                              void* d_out, int out_size) {
    const float* x = (const float*)d_in[0];
    const float* W = (const float*)d_in[1];
    float* out = (float*)d_out;

    prep_all<<<XBLOCKS + WBLOCKS, 256>>>(x, W);

    cudaFuncSetAttribute(xorconv_main,
                         cudaFuncAttributeMaxDynamicSharedMemorySize, SMEM_BYTES);
    dim3 gm(HOUT / 2, BDIM, 2);   // 31 row-pairs x 32 images x 2 co-halves
    xorconv_main<<<gm, 256, SMEM_BYTES>>>(out);
}